// round 7
// baseline (speedup 1.0000x reference)
#include <cuda_runtime.h>
#include <cuda_bf16.h>
#include <cstdint>
#include <math.h>

typedef unsigned int u32;
typedef __nv_bfloat16 bf16;

#define S_LEN 2048
#define HID_  2048
#define NH    32
#define NKV   8
#define HD    64
#define LAMBDA_INIT 0.7836057665316245f  // 0.8 - 0.6*exp(-0.3*12)

// ---------------- scratch (device globals; no allocation allowed) ----------------
__device__ float g_q[(size_t)S_LEN * 4096];    // q proj fp32 (pre-rope)
__device__ float g_k[(size_t)S_LEN * 1024];
__device__ float g_v[(size_t)S_LEN * 512];
__device__ u32   g_qp[(size_t)S_LEN * 4096];   // attention-internal packed hi|lo
__device__ u32   g_kp[(size_t)S_LEN * 1024];
__device__ u32   g_vp[(size_t)S_LEN * 512];
// hi/lo bf16 planes for GEMM operands
__device__ bf16  g_hs_h[(size_t)S_LEN * HID_],  g_hs_l[(size_t)S_LEN * HID_];
__device__ bf16  g_wq_h[(size_t)4096 * HID_],   g_wq_l[(size_t)4096 * HID_];
__device__ bf16  g_wk_h[(size_t)1024 * HID_],   g_wk_l[(size_t)1024 * HID_];
__device__ bf16  g_wv_h[(size_t)512 * HID_],    g_wv_l[(size_t)512 * HID_];
__device__ bf16  g_wo_h[(size_t)HID_ * HID_],   g_wo_l[(size_t)HID_ * HID_];
__device__ bf16  g_at_h[(size_t)S_LEN * HID_],  g_at_l[(size_t)S_LEN * HID_];
__device__ float g_lambda;

// ================= common helpers =================
__device__ __forceinline__ u32 pack_bf(float x) {
    bf16 h = __float2bfloat16(x);
    float hf = __bfloat162float(h);
    bf16 l = __float2bfloat16(x - hf);
    unsigned short hs = *reinterpret_cast<unsigned short*>(&h);
    unsigned short ls = *reinterpret_cast<unsigned short*>(&l);
    return ((u32)hs << 16) | (u32)ls;
}

__device__ __forceinline__ void split2(float x, float y, u32& hi, u32& lo) {
    float hx = __bfloat162float(__float2bfloat16(x));
    float hy = __bfloat162float(__float2bfloat16(y));
    __nv_bfloat162 hp = __floats2bfloat162_rn(hx, hy);
    __nv_bfloat162 lp = __floats2bfloat162_rn(x - hx, y - hy);
    hi = *reinterpret_cast<u32*>(&hp);
    lo = *reinterpret_cast<u32*>(&lp);
}

__device__ __forceinline__ void mma_bf16(float* c, const u32* a, const u32* b) {
    asm volatile(
        "mma.sync.aligned.m16n8k16.row.col.f32.bf16.bf16.f32 "
        "{%0,%1,%2,%3}, {%4,%5,%6,%7}, {%8,%9}, {%0,%1,%2,%3};"
        : "+f"(c[0]), "+f"(c[1]), "+f"(c[2]), "+f"(c[3])
        : "r"(a[0]), "r"(a[1]), "r"(a[2]), "r"(a[3]), "r"(b[0]), "r"(b[1]));
}

__device__ __forceinline__ void ldsm4(u32& r0, u32& r1, u32& r2, u32& r3, u32 saddr) {
    asm volatile("ldmatrix.sync.aligned.m8n8.x4.shared.b16 {%0,%1,%2,%3}, [%4];"
                 : "=r"(r0), "=r"(r1), "=r"(r2), "=r"(r3) : "r"(saddr));
}

__device__ __forceinline__ void cp_async16s(u32 saddr, const void* gptr) {
    asm volatile("cp.async.cg.shared.global [%0], [%1], 16;" :: "r"(saddr), "l"(gptr));
}

// ======== bf16 split GEMM: deinterleaved hi/lo planes + ldmatrix + cp.async ========
// C[M,N] = A[M,K] @ B[N,K]^T. Block 128x128, BK=32, 256 thr (8 warps, warp 64x32).
// smem per stage: 4 planes (Ah,Al,Bh,Bl), each 128 rows x 80B (64B data + 16B pad).
#define ROWB 80
#define PLANE_B (128 * ROWB)                 // 10240 B
#define STAGE_B (4 * PLANE_B)                // 40960 B
#define GEMM_SMEM_BYTES (2 * STAGE_B)        // 81920 B

__global__ void __launch_bounds__(256) gemm_ld(const bf16* __restrict__ Ah,
                                               const bf16* __restrict__ Al,
                                               const bf16* __restrict__ Bh,
                                               const bf16* __restrict__ Bl,
                                               float* __restrict__ C,
                                               int M, int N, int K) {
    extern __shared__ char smem_raw[];
    const u32 sbase = (u32)__cvta_generic_to_shared(smem_raw);

    const int tid  = threadIdx.x;
    const int lane = tid & 31;
    const int warp = tid >> 5;
    const int wm = (warp >> 2) * 64;
    const int wn = (warp & 3) * 32;
    const int m0 = blockIdx.y * 128;
    const int n0 = blockIdx.x * 128;
    const int q  = lane & 3;
    const int g  = lane >> 2;

    // cp.async assignments: 512 16B-chunks per plane; thread does 2 per plane.
    int crow[2], ccol[2];
#pragma unroll
    for (int it = 0; it < 2; it++) {
        int idx = tid * 2 + it;           // 0..511
        crow[it] = idx >> 2; ccol[it] = (idx & 3) * 16;  // byte col within 64B row
    }

    // ldmatrix per-lane address components (bytes, within a plane)
    // A (mi): m0 rows+g k0 | m1 rows+8 | m2 +16B | m3 rows+8 +16B
    int aoff[4];
#pragma unroll
    for (int mi = 0; mi < 4; mi++)
        aoff[mi] = (wm + mi * 16 + (lane & 7) + ((lane >> 3) & 1) * 8) * ROWB
                 + ((lane >> 4) & 1) * 16;
    // B (pair p covers nj=2p,2p+1): m0 rows n0p+g | m1 +16B | m2 rows+8 | m3 rows+8+16B
    int boff[2];
#pragma unroll
    for (int p = 0; p < 2; p++)
        boff[p] = (wn + p * 16 + (lane & 7) + ((lane >> 4) & 1) * 8) * ROWB
                + ((lane >> 3) & 1) * 16;

    float acc[4][4][4] = {};

    auto issue = [&](int stg, int k0) {
        u32 s = sbase + stg * STAGE_B;
#pragma unroll
        for (int it = 0; it < 2; it++) {
            int r = crow[it], cb = ccol[it];
            size_t ga = (size_t)(m0 + r) * K + k0 + cb / 2;   // bf16 elements
            size_t gb = (size_t)(n0 + r) * K + k0 + cb / 2;
            u32 sa = s + r * ROWB + cb;
            cp_async16s(sa,                Ah + ga);
            cp_async16s(sa + PLANE_B,      Al + ga);
            cp_async16s(sa + 2 * PLANE_B,  Bh + gb);
            cp_async16s(sa + 3 * PLANE_B,  Bl + gb);
        }
        asm volatile("cp.async.commit_group;");
    };

    issue(0, 0);
    const int nk = K >> 5;
    for (int i = 0; i < nk; i++) {
        if (i + 1 < nk) {
            issue((i + 1) & 1, (i + 1) << 5);
            asm volatile("cp.async.wait_group 1;");
        } else {
            asm volatile("cp.async.wait_group 0;");
        }
        __syncthreads();

        const u32 s = sbase + (i & 1) * STAGE_B;
#pragma unroll
        for (int kk = 0; kk < 2; kk++) {          // two k16 steps; byte offset 32*kk
            const int kb = kk * 32;
            u32 ah[4][4], al[4][4], bh[2][4], bl[2][4];
#pragma unroll
            for (int mi = 0; mi < 4; mi++) {
                ldsm4(ah[mi][0], ah[mi][1], ah[mi][2], ah[mi][3], s + aoff[mi] + kb);
                ldsm4(al[mi][0], al[mi][1], al[mi][2], al[mi][3], s + PLANE_B + aoff[mi] + kb);
            }
#pragma unroll
            for (int p = 0; p < 2; p++) {
                ldsm4(bh[p][0], bh[p][1], bh[p][2], bh[p][3], s + 2 * PLANE_B + boff[p] + kb);
                ldsm4(bl[p][0], bl[p][1], bl[p][2], bl[p][3], s + 3 * PLANE_B + boff[p] + kb);
            }
#pragma unroll
            for (int mi = 0; mi < 4; mi++)
#pragma unroll
                for (int nj = 0; nj < 4; nj++) {
                    const u32* BH = &bh[nj >> 1][(nj & 1) * 2];
                    const u32* BL = &bl[nj >> 1][(nj & 1) * 2];
                    mma_bf16(acc[mi][nj], ah[mi], BH);
                    mma_bf16(acc[mi][nj], ah[mi], BL);
                    mma_bf16(acc[mi][nj], al[mi], BH);
                }
        }
        __syncthreads();
    }

#pragma unroll
    for (int mi = 0; mi < 4; mi++) {
        int r = m0 + wm + mi * 16 + g;
#pragma unroll
        for (int nj = 0; nj < 4; nj++) {
            int c = n0 + wn + nj * 8 + 2 * q;
            *(float2*)(C + (size_t)r * N + c)       = make_float2(acc[mi][nj][0], acc[mi][nj][1]);
            *(float2*)(C + (size_t)(r + 8) * N + c) = make_float2(acc[mi][nj][2], acc[mi][nj][3]);
        }
    }
}

// ---------------- pack fp32 -> hi/lo planes ----------------
__global__ void pack_planes(const float* __restrict__ src, bf16* __restrict__ hi,
                            bf16* __restrict__ lo, int n) {
    int i = blockIdx.x * blockDim.x + threadIdx.x;
    if (i >= n) return;
    float x = src[i];
    bf16 h = __float2bfloat16(x);
    hi[i] = h;
    lo[i] = __float2bfloat16(x - __bfloat162float(h));
}

// ---------------- RoPE + pack (interleaved, attention-internal) ----------------
__global__ void rope_pack_kernel(const float* __restrict__ src, u32* __restrict__ dst,
                                 int nslots, int rowstride, int total, float prescale) {
    int idx = blockIdx.x * blockDim.x + threadIdx.x;
    if (idx >= total) return;
    int dh = idx & 31;
    int slot = (idx >> 5) % nslots;
    int s = idx / (nslots << 5);
    float pos = (float)s;
    float invf = expf(-(2.0f * dh / 64.0f) * 9.210340371976184f);
    float ang = pos * invf;
    float c = cosf(ang), sn = sinf(ang);
    const float* row = src + (size_t)s * rowstride + slot * 64;
    u32* drow = dst + (size_t)s * rowstride + slot * 64;
    float x0 = row[dh], x1 = row[dh + 32];
    float y0 = (x0 * c - x1 * sn) * prescale;
    float y1 = (x1 * c + x0 * sn) * prescale;
    drow[dh]      = pack_bf(y0);
    drow[dh + 32] = pack_bf(y1);
}

// ---------------- pack V interleaved ----------------
__global__ void pack_kernel(const float* __restrict__ src, u32* __restrict__ dst, int n) {
    int i = blockIdx.x * blockDim.x + threadIdx.x;
    if (i < n) dst[i] = pack_bf(src[i]);
}

// ---------------- lambda_full ----------------
__global__ void lambda_kernel(const float* lq1, const float* lk1,
                              const float* lq2, const float* lk2) {
    float s1 = 0.f, s2 = 0.f;
    for (int i = threadIdx.x; i < 64; i += 32) {
        s1 += lq1[i] * lk1[i];
        s2 += lq2[i] * lk2[i];
    }
#pragma unroll
    for (int o = 16; o; o >>= 1) {
        s1 += __shfl_xor_sync(0xffffffffu, s1, o);
        s2 += __shfl_xor_sync(0xffffffffu, s2, o);
    }
    if (threadIdx.x == 0) g_lambda = expf(s1) - expf(s2) + LAMBDA_INIT;
}

// ============ fused dual flash attention (tensor core) + diff + RMSNorm ============
#define KSTR 68
#define ATT_SMEM_BYTES (3 * 64 * KSTR * 4)

__device__ __forceinline__ void online_softmax(float (&s)[8][4], float* m, float* l,
                                               float (&O)[8][4]) {
    float mx0 = -1e30f, mx1 = -1e30f;
#pragma unroll
    for (int jn = 0; jn < 8; jn++) {
        mx0 = fmaxf(mx0, fmaxf(s[jn][0], s[jn][1]));
        mx1 = fmaxf(mx1, fmaxf(s[jn][2], s[jn][3]));
    }
    mx0 = fmaxf(mx0, __shfl_xor_sync(0xffffffffu, mx0, 1));
    mx0 = fmaxf(mx0, __shfl_xor_sync(0xffffffffu, mx0, 2));
    mx1 = fmaxf(mx1, __shfl_xor_sync(0xffffffffu, mx1, 1));
    mx1 = fmaxf(mx1, __shfl_xor_sync(0xffffffffu, mx1, 2));
    float mn0 = fmaxf(m[0], mx0), mn1 = fmaxf(m[1], mx1);
    float c0 = __expf(m[0] - mn0), c1 = __expf(m[1] - mn1);
    float rs0 = 0.f, rs1 = 0.f;
#pragma unroll
    for (int jn = 0; jn < 8; jn++) {
        s[jn][0] = __expf(s[jn][0] - mn0);
        s[jn][1] = __expf(s[jn][1] - mn0);
        s[jn][2] = __expf(s[jn][2] - mn1);
        s[jn][3] = __expf(s[jn][3] - mn1);
        rs0 += s[jn][0] + s[jn][1];
        rs1 += s[jn][2] + s[jn][3];
    }
    rs0 += __shfl_xor_sync(0xffffffffu, rs0, 1);
    rs0 += __shfl_xor_sync(0xffffffffu, rs0, 2);
    rs1 += __shfl_xor_sync(0xffffffffu, rs1, 1);
    rs1 += __shfl_xor_sync(0xffffffffu, rs1, 2);
    l[0] = l[0] * c0 + rs0; m[0] = mn0;
    l[1] = l[1] * c1 + rs1; m[1] = mn1;
#pragma unroll
    for (int jn = 0; jn < 8; jn++) {
        O[jn][0] *= c0; O[jn][1] *= c0;
        O[jn][2] *= c1; O[jn][3] *= c1;
    }
}

__global__ void __launch_bounds__(128) diff_attn_mma(const float* __restrict__ subln_w) {
    extern __shared__ u32 smem_u[];
    u32* sK1 = smem_u;
    u32* sK2 = sK1 + 64 * KSTR;
    u32* sV  = sK2 + 64 * KSTR;

    const int qb = blockIdx.x, h = blockIdx.y;
    const int hk = h >> 2;
    const int tid = threadIdx.x;
    const int warp = tid >> 5, lane = tid & 31;
    const int g = lane >> 2, q = lane & 3;

    const int r0 = qb * 64 + warp * 16 + g;
    const int r1 = r0 + 8;

    u32 qh1[4][4], ql1[4][4], qh2[4][4], ql2[4][4];
    {
        const u32* b0 = g_qp + (size_t)r0 * 4096 + h * 64;
        const u32* b1 = g_qp + (size_t)r1 * 4096 + h * 64;
#pragma unroll
        for (int t = 0; t < 4; t++) {
            int kk = 16 * t;
            uint2 w;
            w = *(const uint2*)(b0 + kk + 2 * q);
            qh1[t][0] = __byte_perm(w.x, w.y, 0x7632); ql1[t][0] = __byte_perm(w.x, w.y, 0x5410);
            w = *(const uint2*)(b1 + kk + 2 * q);
            qh1[t][1] = __byte_perm(w.x, w.y, 0x7632); ql1[t][1] = __byte_perm(w.x, w.y, 0x5410);
            w = *(const uint2*)(b0 + kk + 8 + 2 * q);
            qh1[t][2] = __byte_perm(w.x, w.y, 0x7632); ql1[t][2] = __byte_perm(w.x, w.y, 0x5410);
            w = *(const uint2*)(b1 + kk + 8 + 2 * q);
            qh1[t][3] = __byte_perm(w.x, w.y, 0x7632); ql1[t][3] = __byte_perm(w.x, w.y, 0x5410);
            w = *(const uint2*)(b0 + 2048 + kk + 2 * q);
            qh2[t][0] = __byte_perm(w.x, w.y, 0x7632); ql2[t][0] = __byte_perm(w.x, w.y, 0x5410);
            w = *(const uint2*)(b1 + 2048 + kk + 2 * q);
            qh2[t][1] = __byte_perm(w.x, w.y, 0x7632); ql2[t][1] = __byte_perm(w.x, w.y, 0x5410);
            w = *(const uint2*)(b0 + 2048 + kk + 8 + 2 * q);
            qh2[t][2] = __byte_perm(w.x, w.y, 0x7632); ql2[t][2] = __byte_perm(w.x, w.y, 0x5410);
            w = *(const uint2*)(b1 + 2048 + kk + 8 + 2 * q);
            qh2[t][3] = __byte_perm(w.x, w.y, 0x7632); ql2[t][3] = __byte_perm(w.x, w.y, 0x5410);
        }
    }

    float O1[8][4] = {}, O2[8][4] = {};
    float m1[2] = {-1e30f, -1e30f}, l1[2] = {0.f, 0.f};
    float m2[2] = {-1e30f, -1e30f}, l2[2] = {0.f, 0.f};

    for (int kb = 0; kb <= qb; kb++) {
        __syncthreads();
        for (int idx = tid; idx < 1024; idx += 128) {
            int row = idx >> 4, d4 = (idx & 15) * 4;
            size_t gr = (size_t)(kb * 64 + row);
            *(uint4*)&sK1[row * KSTR + d4] = *(const uint4*)(g_kp + gr * 1024 + hk * 64 + d4);
            *(uint4*)&sK2[row * KSTR + d4] = *(const uint4*)(g_kp + gr * 1024 + 512 + hk * 64 + d4);
            *(uint4*)&sV [row * KSTR + d4] = *(const uint4*)(g_vp + gr * 512 + hk * 64 + d4);
        }
        __syncthreads();

        float s1[8][4] = {}, s2[8][4] = {};
#pragma unroll
        for (int t = 0; t < 4; t++) {
            int kk = 16 * t;
#pragma unroll
            for (int jn = 0; jn < 8; jn++) {
                int n = 8 * jn + g;
                u32 bh[2], bl[2];
                uint2 w0 = *(const uint2*)&sK1[n * KSTR + kk + 2 * q];
                uint2 w1 = *(const uint2*)&sK1[n * KSTR + kk + 8 + 2 * q];
                bh[0] = __byte_perm(w0.x, w0.y, 0x7632); bl[0] = __byte_perm(w0.x, w0.y, 0x5410);
                bh[1] = __byte_perm(w1.x, w1.y, 0x7632); bl[1] = __byte_perm(w1.x, w1.y, 0x5410);
                mma_bf16(s1[jn], qh1[t], bh);
                mma_bf16(s1[jn], qh1[t], bl);
                mma_bf16(s1[jn], ql1[t], bh);
                w0 = *(const uint2*)&sK2[n * KSTR + kk + 2 * q];
                w1 = *(const uint2*)&sK2[n * KSTR + kk + 8 + 2 * q];
                bh[0] = __byte_perm(w0.x, w0.y, 0x7632); bl[0] = __byte_perm(w0.x, w0.y, 0x5410);
                bh[1] = __byte_perm(w1.x, w1.y, 0x7632); bl[1] = __byte_perm(w1.x, w1.y, 0x5410);
                mma_bf16(s2[jn], qh2[t], bh);
                mma_bf16(s2[jn], qh2[t], bl);
                mma_bf16(s2[jn], ql2[t], bh);
            }
        }

        if (kb == qb) {
#pragma unroll
            for (int jn = 0; jn < 8; jn++) {
                int c0 = kb * 64 + 8 * jn + 2 * q;
                if (c0 > r0)     { s1[jn][0] = -1e30f; s2[jn][0] = -1e30f; }
                if (c0 + 1 > r0) { s1[jn][1] = -1e30f; s2[jn][1] = -1e30f; }
                if (c0 > r1)     { s1[jn][2] = -1e30f; s2[jn][2] = -1e30f; }
                if (c0 + 1 > r1) { s1[jn][3] = -1e30f; s2[jn][3] = -1e30f; }
            }
        }

        online_softmax(s1, m1, l1, O1);
        online_softmax(s2, m2, l2, O2);

#pragma unroll
        for (int t = 0; t < 4; t++) {
            int kk = 16 * t;
            u32 p1h[4], p1l[4], p2h[4], p2l[4];
            split2(s1[2*t][0],   s1[2*t][1],   p1h[0], p1l[0]);
            split2(s1[2*t][2],   s1[2*t][3],   p1h[1], p1l[1]);
            split2(s1[2*t+1][0], s1[2*t+1][1], p1h[2], p1l[2]);
            split2(s1[2*t+1][2], s1[2*t+1][3], p1h[3], p1l[3]);
            split2(s2[2*t][0],   s2[2*t][1],   p2h[0], p2l[0]);
            split2(s2[2*t][2],   s2[2*t][3],   p2h[1], p2l[1]);
            split2(s2[2*t+1][0], s2[2*t+1][1], p2h[2], p2l[2]);
            split2(s2[2*t+1][2], s2[2*t+1][3], p2h[3], p2l[3]);
#pragma unroll
            for (int jn = 0; jn < 8; jn++) {
                int n = 8 * jn + g;
                u32 w0 = sV[(kk + 2 * q)     * KSTR + n];
                u32 w1 = sV[(kk + 2 * q + 1) * KSTR + n];
                u32 w2 = sV[(kk + 8 + 2 * q)     * KSTR + n];
                u32 w3 = sV[(kk + 8 + 2 * q + 1) * KSTR + n];
                u32 vh[2] = {__byte_perm(w0, w1, 0x7632), __byte_perm(w2, w3, 0x7632)};
                u32 vl[2] = {__byte_perm(w0, w1, 0x5410), __byte_perm(w2, w3, 0x5410)};
                mma_bf16(O1[jn], p1h, vh);
                mma_bf16(O1[jn], p1h, vl);
                mma_bf16(O1[jn], p1l, vh);
                mma_bf16(O2[jn], p2h, vh);
                mma_bf16(O2[jn], p2h, vl);
                mma_bf16(O2[jn], p2l, vh);
            }
        }
    }

    // epilogue: diff, RMSNorm, subln, (1-lambda_init); write hi/lo planes for Wo gemm
    const float lam = g_lambda;
    const float il10 = 1.f / l1[0], il11 = 1.f / l1[1];
    const float il20 = 1.f / l2[0], il21 = 1.f / l2[1];
    float oA[8][2], oB[8][2];
    float ss0 = 0.f, ss1 = 0.f;
#pragma unroll
    for (int jn = 0; jn < 8; jn++) {
        float a0 = O1[jn][0] * il10 - lam * (O2[jn][0] * il20);
        float a1 = O1[jn][1] * il10 - lam * (O2[jn][1] * il20);
        float b0 = O1[jn][2] * il11 - lam * (O2[jn][2] * il21);
        float b1 = O1[jn][3] * il11 - lam * (O2[jn][3] * il21);
        oA[jn][0] = a0; oA[jn][1] = a1;
        oB[jn][0] = b0; oB[jn][1] = b1;
        ss0 += a0 * a0 + a1 * a1;
        ss1 += b0 * b0 + b1 * b1;
    }
    ss0 += __shfl_xor_sync(0xffffffffu, ss0, 1);
    ss0 += __shfl_xor_sync(0xffffffffu, ss0, 2);
    ss1 += __shfl_xor_sync(0xffffffffu, ss1, 1);
    ss1 += __shfl_xor_sync(0xffffffffu, ss1, 2);
    float k0 = rsqrtf(ss0 * (1.0f / 64.0f) + 1e-6f) * (1.0f - LAMBDA_INIT);
    float k1 = rsqrtf(ss1 * (1.0f / 64.0f) + 1e-6f) * (1.0f - LAMBDA_INIT);
#pragma unroll
    for (int jn = 0; jn < 8; jn++) {
        int col = 8 * jn + 2 * q;
        float w0 = subln_w[col], w1 = subln_w[col + 1];
        float a0 = oA[jn][0] * k0 * w0, a1 = oA[jn][1] * k0 * w1;
        float b0 = oB[jn][0] * k1 * w0, b1 = oB[jn][1] * k1 * w1;
        u32 ahi, alo, bhi, blo;
        split2(a0, a1, ahi, alo);
        split2(b0, b1, bhi, blo);
        size_t i0 = (size_t)r0 * HID_ + h * 64 + col;
        size_t i1 = (size_t)r1 * HID_ + h * 64 + col;
        *(u32*)(g_at_h + i0) = ahi; *(u32*)(g_at_l + i0) = alo;
        *(u32*)(g_at_h + i1) = bhi; *(u32*)(g_at_l + i1) = blo;
    }
}

// ---------------- launch ----------------
extern "C" void kernel_launch(void* const* d_in, const int* in_sizes, int n_in,
                              void* d_out, int out_size) {
    const float* hs   = (const float*)d_in[0];
    const float* Wq   = (const float*)d_in[1];
    const float* Wk   = (const float*)d_in[2];
    const float* Wv   = (const float*)d_in[3];
    const float* Wo   = (const float*)d_in[4];
    const float* lq1  = (const float*)d_in[5];
    const float* lk1  = (const float*)d_in[6];
    const float* lq2  = (const float*)d_in[7];
    const float* lk2  = (const float*)d_in[8];
    const float* subw = (const float*)d_in[9];
    float* out = (float*)d_out;

    void *pq, *pk, *pv, *pqp, *pkp, *pvp;
    void *hsh, *hsl, *wqh, *wql, *wkh, *wkl, *wvh, *wvl, *woh, *wol, *ath, *atl;
    cudaGetSymbolAddress(&pq, g_q);
    cudaGetSymbolAddress(&pk, g_k);
    cudaGetSymbolAddress(&pv, g_v);
    cudaGetSymbolAddress(&pqp, g_qp);
    cudaGetSymbolAddress(&pkp, g_kp);
    cudaGetSymbolAddress(&pvp, g_vp);
    cudaGetSymbolAddress(&hsh, g_hs_h); cudaGetSymbolAddress(&hsl, g_hs_l);
    cudaGetSymbolAddress(&wqh, g_wq_h); cudaGetSymbolAddress(&wql, g_wq_l);
    cudaGetSymbolAddress(&wkh, g_wk_h); cudaGetSymbolAddress(&wkl, g_wk_l);
    cudaGetSymbolAddress(&wvh, g_wv_h); cudaGetSymbolAddress(&wvl, g_wv_l);
    cudaGetSymbolAddress(&woh, g_wo_h); cudaGetSymbolAddress(&wol, g_wo_l);
    cudaGetSymbolAddress(&ath, g_at_h); cudaGetSymbolAddress(&atl, g_at_l);
    cudaFuncSetAttribute(diff_attn_mma,
                         cudaFuncAttributeMaxDynamicSharedMemorySize, ATT_SMEM_BYTES);
    cudaFuncSetAttribute(gemm_ld,
                         cudaFuncAttributeMaxDynamicSharedMemorySize, GEMM_SMEM_BYTES);

    // pre-pack activations and weights into hi/lo planes
    pack_planes<<<(S_LEN * HID_ + 255) / 256, 256>>>(hs, (bf16*)hsh, (bf16*)hsl, S_LEN * HID_);
    pack_planes<<<(4096 * HID_ + 255) / 256, 256>>>(Wq, (bf16*)wqh, (bf16*)wql, 4096 * HID_);
    pack_planes<<<(1024 * HID_ + 255) / 256, 256>>>(Wk, (bf16*)wkh, (bf16*)wkl, 1024 * HID_);
    pack_planes<<<(512 * HID_ + 255) / 256, 256>>>(Wv, (bf16*)wvh, (bf16*)wvl, 512 * HID_);
    pack_planes<<<(HID_ * HID_ + 255) / 256, 256>>>(Wo, (bf16*)woh, (bf16*)wol, HID_ * HID_);

    // projections
    gemm_ld<<<dim3(4096 / 128, S_LEN / 128), 256, GEMM_SMEM_BYTES>>>(
        (const bf16*)hsh, (const bf16*)hsl, (const bf16*)wqh, (const bf16*)wql,
        (float*)pq, S_LEN, 4096, HID_);
    gemm_ld<<<dim3(1024 / 128, S_LEN / 128), 256, GEMM_SMEM_BYTES>>>(
        (const bf16*)hsh, (const bf16*)hsl, (const bf16*)wkh, (const bf16*)wkl,
        (float*)pk, S_LEN, 1024, HID_);
    gemm_ld<<<dim3(512 / 128, S_LEN / 128), 256, GEMM_SMEM_BYTES>>>(
        (const bf16*)hsh, (const bf16*)hsl, (const bf16*)wvh, (const bf16*)wvl,
        (float*)pv, S_LEN, 512, HID_);

    // rope + pack q (scale 1/8 folded), k; pack v (attention-internal interleaved)
    {
        int tq = S_LEN * 64 * 32;
        rope_pack_kernel<<<(tq + 255) / 256, 256>>>((const float*)pq, (u32*)pqp, 64, 4096, tq, 0.125f);
        int tk = S_LEN * 16 * 32;
        rope_pack_kernel<<<(tk + 255) / 256, 256>>>((const float*)pk, (u32*)pkp, 16, 1024, tk, 1.0f);
        int nv = S_LEN * 512;
        pack_kernel<<<(nv + 255) / 256, 256>>>((const float*)pv, (u32*)pvp, nv);
    }

    lambda_kernel<<<1, 32>>>(lq1, lk1, lq2, lk2);

    diff_attn_mma<<<dim3(S_LEN / 64, NH), 128, ATT_SMEM_BYTES>>>(subw);

    // output projection (attention epilogue already wrote hi/lo planes)
    gemm_ld<<<dim3(HID_ / 128, S_LEN / 128), 256, GEMM_SMEM_BYTES>>>(
        (const bf16*)ath, (const bf16*)atl, (const bf16*)woh, (const bf16*)wol,
        out, S_LEN, HID_, HID_);
}

// round 9
// speedup vs baseline: 1.8614x; 1.8614x over previous
#include <cuda_runtime.h>
#include <cuda_fp16.h>
#include <cstdint>
#include <math.h>

typedef unsigned int u32;

#define S_LEN 2048
#define HID_  2048
#define NQKV  5632            // 4096 (q) + 1024 (k) + 512 (v)
#define LAMBDA_INIT 0.7836057665316245f  // 0.8 - 0.6*exp(-0.3*12)

// ---------------- scratch (device globals; no allocation allowed) ----------------
__device__ float  g_qkv[(size_t)S_LEN * NQKV];     // fused qkv projection, fp32
__device__ __half g_hs_p[(size_t)S_LEN * HID_];    // packed hidden_states
__device__ __half g_w_p[(size_t)NQKV * HID_];      // packed Wq|Wk|Wv (row concat)
__device__ __half g_wo_p[(size_t)HID_ * HID_];     // packed Wo
__device__ __half g_at_p[(size_t)S_LEN * HID_];    // packed pre-Wo activation
__device__ __half g_qph[(size_t)S_LEN * 4096];     // roped q (q1|q2), fp16, q pre-scaled 1/8
__device__ __half g_kph[(size_t)S_LEN * 1024];     // roped k (k1|k2), fp16
__device__ __half g_vth[(size_t)512 * S_LEN];      // V transposed: row = hk*64+d, col = s
__device__ float  g_lambda;

// ================= helpers =================
__device__ __forceinline__ void mma_f16(float* c, const u32* a, const u32* b) {
    asm volatile(
        "mma.sync.aligned.m16n8k16.row.col.f32.f16.f16.f32 "
        "{%0,%1,%2,%3}, {%4,%5,%6,%7}, {%8,%9}, {%0,%1,%2,%3};"
        : "+f"(c[0]), "+f"(c[1]), "+f"(c[2]), "+f"(c[3])
        : "r"(a[0]), "r"(a[1]), "r"(a[2]), "r"(a[3]), "r"(b[0]), "r"(b[1]));
}

__device__ __forceinline__ u32 h2u(float x, float y) {
    __half2 h = __floats2half2_rn(x, y);
    return *reinterpret_cast<u32*>(&h);
}

__device__ __forceinline__ void ldsm4(u32& r0, u32& r1, u32& r2, u32& r3, u32 saddr) {
    asm volatile("ldmatrix.sync.aligned.m8n8.x4.shared.b16 {%0,%1,%2,%3}, [%4];"
                 : "=r"(r0), "=r"(r1), "=r"(r2), "=r"(r3) : "r"(saddr));
}

__device__ __forceinline__ void cp_async16s(u32 saddr, const void* gptr) {
    asm volatile("cp.async.cg.shared.global [%0], [%1], 16;" :: "r"(saddr), "l"(gptr));
}

// ================= fp16 single-pass GEMM =================
// C[M,N] = A[M,K] @ B[N,K]^T ; A,B fp16 planes. Block 128x128, BK=32,
// 256 thr (8 warps, 64x32 warp tiles), 2-stage cp.async, ldmatrix frags.
#define ROWB 80
#define PLANE_B (128 * ROWB)                 // 10240 B
#define STAGE_B (2 * PLANE_B)                // A + B = 20480 B
#define GEMM_SMEM_BYTES (2 * STAGE_B)        // 40960 B

__global__ void __launch_bounds__(256) gemm_f16(const __half* __restrict__ A,
                                                const __half* __restrict__ B,
                                                float* __restrict__ C,
                                                int M, int N, int K) {
    extern __shared__ char smem_raw[];
    const u32 sbase = (u32)__cvta_generic_to_shared(smem_raw);

    const int tid  = threadIdx.x;
    const int lane = tid & 31;
    const int warp = tid >> 5;
    const int wm = (warp >> 2) * 64;
    const int wn = (warp & 3) * 32;
    const int m0 = blockIdx.y * 128;
    const int n0 = blockIdx.x * 128;
    const int q  = lane & 3;
    const int g  = lane >> 2;

    int crow[2], ccol[2];
#pragma unroll
    for (int it = 0; it < 2; it++) {
        int idx = tid * 2 + it;            // 0..511 chunks per plane
        crow[it] = idx >> 2; ccol[it] = (idx & 3) * 16;
    }

    int aoff[4];
#pragma unroll
    for (int mi = 0; mi < 4; mi++)
        aoff[mi] = (wm + mi * 16 + (lane & 7) + ((lane >> 3) & 1) * 8) * ROWB
                 + ((lane >> 4) & 1) * 16;
    int boff[2];
#pragma unroll
    for (int p = 0; p < 2; p++)
        boff[p] = (wn + p * 16 + (lane & 7) + ((lane >> 4) & 1) * 8) * ROWB
                + ((lane >> 3) & 1) * 16;

    float acc[4][4][4] = {};

    auto issue = [&](int stg, int k0) {
        u32 s = sbase + stg * STAGE_B;
#pragma unroll
        for (int it = 0; it < 2; it++) {
            int r = crow[it], cb = ccol[it];
            size_t ga = (size_t)(m0 + r) * K + k0 + cb / 2;
            size_t gb = (size_t)(n0 + r) * K + k0 + cb / 2;
            u32 sa = s + r * ROWB + cb;
            cp_async16s(sa,           A + ga);
            cp_async16s(sa + PLANE_B, B + gb);
        }
        asm volatile("cp.async.commit_group;");
    };

    issue(0, 0);
    const int nk = K >> 5;
    for (int i = 0; i < nk; i++) {
        if (i + 1 < nk) {
            issue((i + 1) & 1, (i + 1) << 5);
            asm volatile("cp.async.wait_group 1;");
        } else {
            asm volatile("cp.async.wait_group 0;");
        }
        __syncthreads();

        const u32 s = sbase + (i & 1) * STAGE_B;
#pragma unroll
        for (int kk = 0; kk < 2; kk++) {
            const int kb = kk * 32;
            u32 ah[4][4], bh[2][4];
#pragma unroll
            for (int mi = 0; mi < 4; mi++)
                ldsm4(ah[mi][0], ah[mi][1], ah[mi][2], ah[mi][3], s + aoff[mi] + kb);
#pragma unroll
            for (int p = 0; p < 2; p++)
                ldsm4(bh[p][0], bh[p][1], bh[p][2], bh[p][3], s + PLANE_B + boff[p] + kb);
#pragma unroll
            for (int mi = 0; mi < 4; mi++)
#pragma unroll
                for (int nj = 0; nj < 4; nj++)
                    mma_f16(acc[mi][nj], ah[mi], &bh[nj >> 1][(nj & 1) * 2]);
        }
        __syncthreads();
    }

#pragma unroll
    for (int mi = 0; mi < 4; mi++) {
        int r = m0 + wm + mi * 16 + g;
#pragma unroll
        for (int nj = 0; nj < 4; nj++) {
            int c = n0 + wn + nj * 8 + 2 * q;
            *(float2*)(C + (size_t)r * N + c)       = make_float2(acc[mi][nj][0], acc[mi][nj][1]);
            *(float2*)(C + (size_t)(r + 8) * N + c) = make_float2(acc[mi][nj][2], acc[mi][nj][3]);
        }
    }
}

// ---------------- pack fp32 -> fp16 (vectorized by pairs) ----------------
__global__ void pack_half2(const float2* __restrict__ src, u32* __restrict__ dst, int n2) {
    int i = blockIdx.x * blockDim.x + threadIdx.x;
    if (i >= n2) return;
    float2 v = src[i];
    dst[i] = h2u(v.x, v.y);
}

// ---------------- RoPE + fp16 pack ----------------
// position_ids == arange(S) for B=1. Thread handles the (d, d+32) rotation pair.
__global__ void rope_pack_half(const float* __restrict__ src, __half* __restrict__ dst,
                               int nslots, int srcstride, int dststride,
                               int total, float prescale) {
    int idx = blockIdx.x * blockDim.x + threadIdx.x;
    if (idx >= total) return;
    int dh = idx & 31;
    int slot = (idx >> 5) % nslots;
    int s = idx / (nslots << 5);
    float pos = (float)s;
    float invf = expf(-(2.0f * dh / 64.0f) * 9.210340371976184f);
    float ang = pos * invf;
    float c = cosf(ang), sn = sinf(ang);
    const float* row = src + (size_t)s * srcstride + slot * 64;
    __half* drow = dst + (size_t)s * dststride + slot * 64;
    float x0 = row[dh], x1 = row[dh + 32];
    drow[dh]      = __float2half_rn((x0 * c - x1 * sn) * prescale);
    drow[dh + 32] = __float2half_rn((x1 * c + x0 * sn) * prescale);
}

// ---------------- V transpose + fp16 pack:  g_vth[c][s] = v[s][c] ----------------
__global__ void pack_v_t(const float* __restrict__ src, __half* __restrict__ dst) {
    int idx = blockIdx.x * blockDim.x + threadIdx.x;   // 512 * 2048
    int s = idx & (S_LEN - 1);
    int c = idx >> 11;
    dst[(size_t)c * S_LEN + s] = __float2half_rn(src[(size_t)s * NQKV + 5120 + c]);
}

// ---------------- lambda_full ----------------
__global__ void lambda_kernel(const float* lq1, const float* lk1,
                              const float* lq2, const float* lk2) {
    float s1 = 0.f, s2 = 0.f;
    for (int i = threadIdx.x; i < 64; i += 32) {
        s1 += lq1[i] * lk1[i];
        s2 += lq2[i] * lk2[i];
    }
#pragma unroll
    for (int o = 16; o; o >>= 1) {
        s1 += __shfl_xor_sync(0xffffffffu, s1, o);
        s2 += __shfl_xor_sync(0xffffffffu, s2, o);
    }
    if (threadIdx.x == 0) g_lambda = expf(s1) - expf(s2) + LAMBDA_INIT;
}

// ============ fused dual flash attention (fp16 single-pass) + diff + RMSNorm ============
#define KSTR 36
#define ATT_SMEM_BYTES (3 * 64 * KSTR * 4)   // 27648 B

__device__ __forceinline__ void online_softmax(float (&s)[8][4], float* m, float* l,
                                               float (&O)[8][4]) {
    float mx0 = -1e30f, mx1 = -1e30f;
#pragma unroll
    for (int jn = 0; jn < 8; jn++) {
        mx0 = fmaxf(mx0, fmaxf(s[jn][0], s[jn][1]));
        mx1 = fmaxf(mx1, fmaxf(s[jn][2], s[jn][3]));
    }
    mx0 = fmaxf(mx0, __shfl_xor_sync(0xffffffffu, mx0, 1));
    mx0 = fmaxf(mx0, __shfl_xor_sync(0xffffffffu, mx0, 2));
    mx1 = fmaxf(mx1, __shfl_xor_sync(0xffffffffu, mx1, 1));
    mx1 = fmaxf(mx1, __shfl_xor_sync(0xffffffffu, mx1, 2));
    float mn0 = fmaxf(m[0], mx0), mn1 = fmaxf(m[1], mx1);
    float c0 = __expf(m[0] - mn0), c1 = __expf(m[1] - mn1);
    float rs0 = 0.f, rs1 = 0.f;
#pragma unroll
    for (int jn = 0; jn < 8; jn++) {
        s[jn][0] = __expf(s[jn][0] - mn0);
        s[jn][1] = __expf(s[jn][1] - mn0);
        s[jn][2] = __expf(s[jn][2] - mn1);
        s[jn][3] = __expf(s[jn][3] - mn1);
        rs0 += s[jn][0] + s[jn][1];
        rs1 += s[jn][2] + s[jn][3];
    }
    rs0 += __shfl_xor_sync(0xffffffffu, rs0, 1);
    rs0 += __shfl_xor_sync(0xffffffffu, rs0, 2);
    rs1 += __shfl_xor_sync(0xffffffffu, rs1, 1);
    rs1 += __shfl_xor_sync(0xffffffffu, rs1, 2);
    l[0] = l[0] * c0 + rs0; m[0] = mn0;
    l[1] = l[1] * c1 + rs1; m[1] = mn1;
#pragma unroll
    for (int jn = 0; jn < 8; jn++) {
        O[jn][0] *= c0; O[jn][1] *= c0;
        O[jn][2] *= c1; O[jn][3] *= c1;
    }
}

__global__ void __launch_bounds__(128) diff_attn_f16(const float* __restrict__ subln_w) {
    extern __shared__ u32 smem_u[];
    u32* sK1 = smem_u;
    u32* sK2 = sK1 + 64 * KSTR;
    u32* sV  = sK2 + 64 * KSTR;

    const int qb = blockIdx.x, h = blockIdx.y;
    const int hk = h >> 2;                 // NREP = 4
    const int tid = threadIdx.x;
    const int warp = tid >> 5, lane = tid & 31;
    const int g = lane >> 2, q = lane & 3;

    const int r0 = qb * 64 + warp * 16 + g;
    const int r1 = r0 + 8;

    // Q fragments straight from global fp16 (q pre-scaled by 1/8)
    u32 qa1[4][4], qa2[4][4];
    {
        const u32* b0 = (const u32*)g_qph + (size_t)r0 * 2048 + h * 32;
        const u32* b1 = (const u32*)g_qph + (size_t)r1 * 2048 + h * 32;
#pragma unroll
        for (int t = 0; t < 4; t++) {
            qa1[t][0] = b0[8 * t + q];
            qa1[t][1] = b1[8 * t + q];
            qa1[t][2] = b0[8 * t + 4 + q];
            qa1[t][3] = b1[8 * t + 4 + q];
            qa2[t][0] = b0[1024 + 8 * t + q];
            qa2[t][1] = b1[1024 + 8 * t + q];
            qa2[t][2] = b0[1024 + 8 * t + 4 + q];
            qa2[t][3] = b1[1024 + 8 * t + 4 + q];
        }
    }

    float O1[8][4] = {}, O2[8][4] = {};
    float m1[2] = {-1e30f, -1e30f}, l1[2] = {0.f, 0.f};
    float m2[2] = {-1e30f, -1e30f}, l2[2] = {0.f, 0.f};

    for (int kb = 0; kb <= qb; kb++) {
        __syncthreads();
        // stage K1, K2 (row = kv position, cols = d pairs) and V^T (row = d, cols = s pairs)
        for (int idx = tid; idx < 1536; idx += 128) {
            int arr = idx >> 9;
            int rem = idx & 511;
            int row = rem >> 3;
            int c4  = (rem & 7) * 4;
            uint4 v;
            if (arr == 0) {
                size_t gr = (size_t)(kb * 64 + row);
                v = *(const uint4*)((const u32*)g_kph + gr * 512 + hk * 32 + c4);
                *(uint4*)&sK1[row * KSTR + c4] = v;
            } else if (arr == 1) {
                size_t gr = (size_t)(kb * 64 + row);
                v = *(const uint4*)((const u32*)g_kph + gr * 512 + 256 + hk * 32 + c4);
                *(uint4*)&sK2[row * KSTR + c4] = v;
            } else {
                v = *(const uint4*)((const u32*)g_vth + (size_t)(hk * 64 + row) * 1024 + kb * 32 + c4);
                *(uint4*)&sV[row * KSTR + c4] = v;
            }
        }
        __syncthreads();

        // --- scores, single fp16 pass per stream ---
        float s1[8][4] = {}, s2[8][4] = {};
#pragma unroll
        for (int t = 0; t < 4; t++) {
#pragma unroll
            for (int jn = 0; jn < 8; jn++) {
                int n = 8 * jn + g;
                u32 b1f[2] = { sK1[n * KSTR + 8 * t + q], sK1[n * KSTR + 8 * t + 4 + q] };
                mma_f16(s1[jn], qa1[t], b1f);
                u32 b2f[2] = { sK2[n * KSTR + 8 * t + q], sK2[n * KSTR + 8 * t + 4 + q] };
                mma_f16(s2[jn], qa2[t], b2f);
            }
        }

        if (kb == qb) {
#pragma unroll
            for (int jn = 0; jn < 8; jn++) {
                int c0 = kb * 64 + 8 * jn + 2 * q;
                if (c0 > r0)     { s1[jn][0] = -1e30f; s2[jn][0] = -1e30f; }
                if (c0 + 1 > r0) { s1[jn][1] = -1e30f; s2[jn][1] = -1e30f; }
                if (c0 > r1)     { s1[jn][2] = -1e30f; s2[jn][2] = -1e30f; }
                if (c0 + 1 > r1) { s1[jn][3] = -1e30f; s2[jn][3] = -1e30f; }
            }
        }

        online_softmax(s1, m1, l1, O1);
        online_softmax(s2, m2, l2, O2);

        // --- P @ V (shared V fragments), single fp16 pass ---
#pragma unroll
        for (int t = 0; t < 4; t++) {
            u32 p1[4], p2[4];
            p1[0] = h2u(s1[2*t][0],   s1[2*t][1]);
            p1[1] = h2u(s1[2*t][2],   s1[2*t][3]);
            p1[2] = h2u(s1[2*t+1][0], s1[2*t+1][1]);
            p1[3] = h2u(s1[2*t+1][2], s1[2*t+1][3]);
            p2[0] = h2u(s2[2*t][0],   s2[2*t][1]);
            p2[1] = h2u(s2[2*t][2],   s2[2*t][3]);
            p2[2] = h2u(s2[2*t+1][0], s2[2*t+1][1]);
            p2[3] = h2u(s2[2*t+1][2], s2[2*t+1][3]);
#pragma unroll
            for (int jn = 0; jn < 8; jn++) {
                int n = 8 * jn + g;
                u32 vb[2] = { sV[n * KSTR + 8 * t + q], sV[n * KSTR + 8 * t + 4 + q] };
                mma_f16(O1[jn], p1, vb);
                mma_f16(O2[jn], p2, vb);
            }
        }
    }

    // epilogue: diff, RMSNorm over D, subln, (1-lambda_init); write fp16 for Wo gemm
    const float lam = g_lambda;
    const float il10 = 1.f / l1[0], il11 = 1.f / l1[1];
    const float il20 = 1.f / l2[0], il21 = 1.f / l2[1];
    float oA[8][2], oB[8][2];
    float ss0 = 0.f, ss1 = 0.f;
#pragma unroll
    for (int jn = 0; jn < 8; jn++) {
        float a0 = O1[jn][0] * il10 - lam * (O2[jn][0] * il20);
        float a1 = O1[jn][1] * il10 - lam * (O2[jn][1] * il20);
        float b0 = O1[jn][2] * il11 - lam * (O2[jn][2] * il21);
        float b1 = O1[jn][3] * il11 - lam * (O2[jn][3] * il21);
        oA[jn][0] = a0; oA[jn][1] = a1;
        oB[jn][0] = b0; oB[jn][1] = b1;
        ss0 += a0 * a0 + a1 * a1;
        ss1 += b0 * b0 + b1 * b1;
    }
    ss0 += __shfl_xor_sync(0xffffffffu, ss0, 1);
    ss0 += __shfl_xor_sync(0xffffffffu, ss0, 2);
    ss1 += __shfl_xor_sync(0xffffffffu, ss1, 1);
    ss1 += __shfl_xor_sync(0xffffffffu, ss1, 2);
    float k0 = rsqrtf(ss0 * (1.0f / 64.0f) + 1e-6f) * (1.0f - LAMBDA_INIT);
    float k1 = rsqrtf(ss1 * (1.0f / 64.0f) + 1e-6f) * (1.0f - LAMBDA_INIT);
#pragma unroll
    for (int jn = 0; jn < 8; jn++) {
        int col = 8 * jn + 2 * q;
        float w0 = subln_w[col], w1 = subln_w[col + 1];
        u32 pa = h2u(oA[jn][0] * k0 * w0, oA[jn][1] * k0 * w1);
        u32 pb = h2u(oB[jn][0] * k1 * w0, oB[jn][1] * k1 * w1);
        *(u32*)(g_at_p + (size_t)r0 * HID_ + h * 64 + col) = pa;
        *(u32*)(g_at_p + (size_t)r1 * HID_ + h * 64 + col) = pb;
    }
}

// ---------------- launch ----------------
extern "C" void kernel_launch(void* const* d_in, const int* in_sizes, int n_in,
                              void* d_out, int out_size) {
    const float* hs   = (const float*)d_in[0];
    const float* Wq   = (const float*)d_in[1];
    const float* Wk   = (const float*)d_in[2];
    const float* Wv   = (const float*)d_in[3];
    const float* Wo   = (const float*)d_in[4];
    const float* lq1  = (const float*)d_in[5];
    const float* lk1  = (const float*)d_in[6];
    const float* lq2  = (const float*)d_in[7];
    const float* lk2  = (const float*)d_in[8];
    const float* subw = (const float*)d_in[9];
    float* out = (float*)d_out;

    void *pqkv, *phsp, *pwp, *pwop, *patp, *pqph, *pkph, *pvth;
    cudaGetSymbolAddress(&pqkv, g_qkv);
    cudaGetSymbolAddress(&phsp, g_hs_p);
    cudaGetSymbolAddress(&pwp, g_w_p);
    cudaGetSymbolAddress(&pwop, g_wo_p);
    cudaGetSymbolAddress(&patp, g_at_p);
    cudaGetSymbolAddress(&pqph, g_qph);
    cudaGetSymbolAddress(&pkph, g_kph);
    cudaGetSymbolAddress(&pvth, g_vth);

    // pack inputs to fp16 (Wq|Wk|Wv concatenated row-wise into one weight buffer)
    {
        int n2;
        n2 = S_LEN * HID_ / 2;
        pack_half2<<<(n2 + 255) / 256, 256>>>((const float2*)hs, (u32*)phsp, n2);
        n2 = 4096 * HID_ / 2;
        pack_half2<<<(n2 + 255) / 256, 256>>>((const float2*)Wq, (u32*)pwp, n2);
        n2 = 1024 * HID_ / 2;
        pack_half2<<<(n2 + 255) / 256, 256>>>((const float2*)Wk,
                                              (u32*)pwp + (size_t)4096 * HID_ / 2, n2);
        n2 = 512 * HID_ / 2;
        pack_half2<<<(n2 + 255) / 256, 256>>>((const float2*)Wv,
                                              (u32*)pwp + (size_t)5120 * HID_ / 2, n2);
        n2 = HID_ * HID_ / 2;
        pack_half2<<<(n2 + 255) / 256, 256>>>((const float2*)Wo, (u32*)pwop, n2);
    }

    // fused QKV projection: C[S, 5632]
    gemm_f16<<<dim3(NQKV / 128, S_LEN / 128), 256, GEMM_SMEM_BYTES>>>(
        (const __half*)phsp, (const __half*)pwp, (float*)pqkv, S_LEN, NQKV, HID_);

    // rope + fp16 pack (q: 64 head-slots, scale 1/8 folded; k: 16 slots); V transpose-pack
    {
        int tq = S_LEN * 64 * 32;
        rope_pack_half<<<(tq + 255) / 256, 256>>>((const float*)pqkv, (__half*)pqph,
                                                  64, NQKV, 4096, tq, 0.125f);
        int tk = S_LEN * 16 * 32;
        rope_pack_half<<<(tk + 255) / 256, 256>>>((const float*)pqkv + 4096, (__half*)pkph,
                                                  16, NQKV, 1024, tk, 1.0f);
        int nv = 512 * S_LEN;
        pack_v_t<<<(nv + 255) / 256, 256>>>((const float*)pqkv, (__half*)pvth);
    }

    lambda_kernel<<<1, 32>>>(lq1, lk1, lq2, lk2);

    diff_attn_f16<<<dim3(S_LEN / 64, 32), 128, ATT_SMEM_BYTES>>>(subw);

    // output projection
    gemm_f16<<<dim3(HID_ / 128, S_LEN / 128), 256, GEMM_SMEM_BYTES>>>(
        (const __half*)patp, (const __half*)pwop, out, S_LEN, HID_, HID_);
}

// round 10
// speedup vs baseline: 2.6563x; 1.4270x over previous
#include <cuda_runtime.h>
#include <cuda_fp16.h>
#include <cstdint>
#include <math.h>

typedef unsigned int u32;

#define S_LEN 2048
#define HID_  2048
#define NQKV  5632            // 4096 (q) + 1024 (k) + 512 (v)
#define LAMBDA_INIT 0.7836057665316245f  // 0.8 - 0.6*exp(-0.3*12)
#define Q_PRESCALE 0.18033688011112042f  // 0.125 * log2(e)  (exp2-domain softmax)

// ---------------- scratch (device globals; no allocation allowed) ----------------
__device__ float  g_qkv[(size_t)S_LEN * NQKV];     // fused qkv projection, fp32
__device__ __half g_hs_p[(size_t)S_LEN * HID_];    // packed hidden_states
__device__ __half g_w_p[(size_t)NQKV * HID_];      // packed Wq|Wk|Wv (row concat)
__device__ __half g_wo_p[(size_t)HID_ * HID_];     // packed Wo
__device__ __half g_at_p[(size_t)S_LEN * HID_];    // packed pre-Wo activation
__device__ __half g_qph[(size_t)S_LEN * 4096];     // roped q (q1|q2), fp16, pre-scaled
__device__ __half g_kph[(size_t)S_LEN * 1024];     // roped k (k1|k2), fp16
__device__ __half g_vth[(size_t)512 * S_LEN];      // V transposed: row = hk*64+d, col = s
__device__ float  g_lambda;

// ================= helpers =================
__device__ __forceinline__ void mma_f16(float* c, const u32* a, const u32* b) {
    asm volatile(
        "mma.sync.aligned.m16n8k16.row.col.f32.f16.f16.f32 "
        "{%0,%1,%2,%3}, {%4,%5,%6,%7}, {%8,%9}, {%0,%1,%2,%3};"
        : "+f"(c[0]), "+f"(c[1]), "+f"(c[2]), "+f"(c[3])
        : "r"(a[0]), "r"(a[1]), "r"(a[2]), "r"(a[3]), "r"(b[0]), "r"(b[1]));
}

__device__ __forceinline__ u32 h2u(float x, float y) {
    __half2 h = __floats2half2_rn(x, y);
    return *reinterpret_cast<u32*>(&h);
}

__device__ __forceinline__ void ldsm4(u32& r0, u32& r1, u32& r2, u32& r3, u32 saddr) {
    asm volatile("ldmatrix.sync.aligned.m8n8.x4.shared.b16 {%0,%1,%2,%3}, [%4];"
                 : "=r"(r0), "=r"(r1), "=r"(r2), "=r"(r3) : "r"(saddr));
}

__device__ __forceinline__ void cp_async16s(u32 saddr, const void* gptr) {
    asm volatile("cp.async.cg.shared.global [%0], [%1], 16;" :: "r"(saddr), "l"(gptr));
}

// ================= fp16 single-pass GEMM =================
// C[M,N] = A[M,K] @ B[N,K]^T. Block 128x128, BK=32, 256 thr, 2-stage cp.async.
#define ROWB 80
#define PLANE_B (128 * ROWB)
#define STAGE_B (2 * PLANE_B)
#define GEMM_SMEM_BYTES (2 * STAGE_B)        // 40960 B

__global__ void __launch_bounds__(256) gemm_f16(const __half* __restrict__ A,
                                                const __half* __restrict__ B,
                                                float* __restrict__ C,
                                                int M, int N, int K) {
    extern __shared__ char smem_raw[];
    const u32 sbase = (u32)__cvta_generic_to_shared(smem_raw);

    const int tid  = threadIdx.x;
    const int lane = tid & 31;
    const int warp = tid >> 5;
    const int wm = (warp >> 2) * 64;
    const int wn = (warp & 3) * 32;
    const int m0 = blockIdx.y * 128;
    const int n0 = blockIdx.x * 128;
    const int q  = lane & 3;
    const int g  = lane >> 2;

    int crow[2], ccol[2];
#pragma unroll
    for (int it = 0; it < 2; it++) {
        int idx = tid * 2 + it;
        crow[it] = idx >> 2; ccol[it] = (idx & 3) * 16;
    }

    int aoff[4];
#pragma unroll
    for (int mi = 0; mi < 4; mi++)
        aoff[mi] = (wm + mi * 16 + (lane & 7) + ((lane >> 3) & 1) * 8) * ROWB
                 + ((lane >> 4) & 1) * 16;
    int boff[2];
#pragma unroll
    for (int p = 0; p < 2; p++)
        boff[p] = (wn + p * 16 + (lane & 7) + ((lane >> 4) & 1) * 8) * ROWB
                + ((lane >> 3) & 1) * 16;

    float acc[4][4][4] = {};

    auto issue = [&](int stg, int k0) {
        u32 s = sbase + stg * STAGE_B;
#pragma unroll
        for (int it = 0; it < 2; it++) {
            int r = crow[it], cb = ccol[it];
            size_t ga = (size_t)(m0 + r) * K + k0 + cb / 2;
            size_t gb = (size_t)(n0 + r) * K + k0 + cb / 2;
            u32 sa = s + r * ROWB + cb;
            cp_async16s(sa,           A + ga);
            cp_async16s(sa + PLANE_B, B + gb);
        }
        asm volatile("cp.async.commit_group;");
    };

    issue(0, 0);
    const int nk = K >> 5;
    for (int i = 0; i < nk; i++) {
        if (i + 1 < nk) {
            issue((i + 1) & 1, (i + 1) << 5);
            asm volatile("cp.async.wait_group 1;");
        } else {
            asm volatile("cp.async.wait_group 0;");
        }
        __syncthreads();

        const u32 s = sbase + (i & 1) * STAGE_B;
#pragma unroll
        for (int kk = 0; kk < 2; kk++) {
            const int kb = kk * 32;
            u32 ah[4][4], bh[2][4];
#pragma unroll
            for (int mi = 0; mi < 4; mi++)
                ldsm4(ah[mi][0], ah[mi][1], ah[mi][2], ah[mi][3], s + aoff[mi] + kb);
#pragma unroll
            for (int p = 0; p < 2; p++)
                ldsm4(bh[p][0], bh[p][1], bh[p][2], bh[p][3], s + PLANE_B + boff[p] + kb);
#pragma unroll
            for (int mi = 0; mi < 4; mi++)
#pragma unroll
                for (int nj = 0; nj < 4; nj++)
                    mma_f16(acc[mi][nj], ah[mi], &bh[nj >> 1][(nj & 1) * 2]);
        }
        __syncthreads();
    }

#pragma unroll
    for (int mi = 0; mi < 4; mi++) {
        int r = m0 + wm + mi * 16 + g;
#pragma unroll
        for (int nj = 0; nj < 4; nj++) {
            int c = n0 + wn + nj * 8 + 2 * q;
            *(float2*)(C + (size_t)r * N + c)       = make_float2(acc[mi][nj][0], acc[mi][nj][1]);
            *(float2*)(C + (size_t)(r + 8) * N + c) = make_float2(acc[mi][nj][2], acc[mi][nj][3]);
        }
    }
}

// ---------------- fused pack: hs | Wq | Wk | Wv | Wo -> fp16 ----------------
#define HS_N (S_LEN * HID_ / 2)
#define WQ_N (4096 * HID_ / 2)
#define WK_N (1024 * HID_ / 2)
#define WV_N (512 * HID_ / 2)
#define WO_N (HID_ * HID_ / 2)
#define PACK_TOTAL (HS_N + WQ_N + WK_N + WV_N + WO_N)

__global__ void pack_all(const float2* __restrict__ hs, const float2* __restrict__ Wq,
                         const float2* __restrict__ Wk, const float2* __restrict__ Wv,
                         const float2* __restrict__ Wo) {
    int i = blockIdx.x * blockDim.x + threadIdx.x;
    if (i >= PACK_TOTAL) return;
    const float2* s;
    u32* d;
    if (i < HS_N)                     { s = hs + i;                    d = (u32*)g_hs_p + i; }
    else if (i < HS_N + WQ_N)         { int j = i - HS_N;              s = Wq + j; d = (u32*)g_w_p + j; }
    else if (i < HS_N + WQ_N + WK_N)  { int j = i - HS_N - WQ_N;       s = Wk + j; d = (u32*)g_w_p + WQ_N + j; }
    else if (i < HS_N + WQ_N + WK_N + WV_N) {
        int j = i - HS_N - WQ_N - WK_N;  s = Wv + j; d = (u32*)g_w_p + WQ_N + WK_N + j;
    } else {
        int j = i - HS_N - WQ_N - WK_N - WV_N; s = Wo + j; d = (u32*)g_wo_p + j;
    }
    float2 v = *s;
    *d = h2u(v.x, v.y);
}

// ---------------- fused rope(q) | rope(k) | transpose-pack(v) ----------------
// position_ids == arange(S) for B=1. q prescaled by 0.125*log2e (exp2 softmax).
#define RQ_N (S_LEN * 64 * 32)
#define RK_N (S_LEN * 16 * 32)
#define RV_N (512 * S_LEN)
#define ROPE_TOTAL (RQ_N + RK_N + RV_N)

__global__ void rope_all() {
    int i = blockIdx.x * blockDim.x + threadIdx.x;
    if (i >= ROPE_TOTAL) return;
    if (i < RQ_N + RK_N) {
        int nslots, srcoff, dststride;
        float prescale;
        int idx;
        if (i < RQ_N) { idx = i;        nslots = 64; srcoff = 0;    dststride = 4096; prescale = Q_PRESCALE; }
        else          { idx = i - RQ_N; nslots = 16; srcoff = 4096; dststride = 1024; prescale = 1.0f; }
        int dh = idx & 31;
        int slot = (idx >> 5) % nslots;
        int s = idx / (nslots << 5);
        float invf = expf(-(2.0f * dh / 64.0f) * 9.210340371976184f);
        float ang = (float)s * invf;
        float c = cosf(ang), sn = sinf(ang);
        const float* row = g_qkv + (size_t)s * NQKV + srcoff + slot * 64;
        __half* drow = (i < RQ_N ? g_qph : g_kph) + (size_t)s * dststride + slot * 64;
        float x0 = row[dh], x1 = row[dh + 32];
        drow[dh]      = __float2half_rn((x0 * c - x1 * sn) * prescale);
        drow[dh + 32] = __float2half_rn((x1 * c + x0 * sn) * prescale);
    } else {
        int j = i - RQ_N - RK_N;
        int s = j & (S_LEN - 1);
        int c = j >> 11;
        g_vth[(size_t)c * S_LEN + s] =
            __float2half_rn(g_qkv[(size_t)s * NQKV + 5120 + c]);
    }
}

// ---------------- lambda_full ----------------
__global__ void lambda_kernel(const float* lq1, const float* lk1,
                              const float* lq2, const float* lk2) {
    float s1 = 0.f, s2 = 0.f;
    for (int i = threadIdx.x; i < 64; i += 32) {
        s1 += lq1[i] * lk1[i];
        s2 += lq2[i] * lk2[i];
    }
#pragma unroll
    for (int o = 16; o; o >>= 1) {
        s1 += __shfl_xor_sync(0xffffffffu, s1, o);
        s2 += __shfl_xor_sync(0xffffffffu, s2, o);
    }
    if (threadIdx.x == 0) g_lambda = expf(s1) - expf(s2) + LAMBDA_INIT;
}

// ============ fused dual flash attention: fp16 mma, cp.async double buffer, ============
// ============ causal pairing (CTA does qb=bx then qb=31-bx), exp2 softmax   ============
#define KSTR 36
#define TILE_U (64 * KSTR)                   // u32 per array
#define STAGE_U (3 * TILE_U)                 // K1 + K2 + V
#define ATT_SMEM_BYTES (2 * STAGE_U * 4)     // 55296 B

__device__ __forceinline__ void online_softmax2(float (&s)[8][4], float* m, float* l,
                                                float (&O)[8][4]) {
    float mx0 = -1e30f, mx1 = -1e30f;
#pragma unroll
    for (int jn = 0; jn < 8; jn++) {
        mx0 = fmaxf(mx0, fmaxf(s[jn][0], s[jn][1]));
        mx1 = fmaxf(mx1, fmaxf(s[jn][2], s[jn][3]));
    }
    mx0 = fmaxf(mx0, __shfl_xor_sync(0xffffffffu, mx0, 1));
    mx0 = fmaxf(mx0, __shfl_xor_sync(0xffffffffu, mx0, 2));
    mx1 = fmaxf(mx1, __shfl_xor_sync(0xffffffffu, mx1, 1));
    mx1 = fmaxf(mx1, __shfl_xor_sync(0xffffffffu, mx1, 2));
    float mn0 = fmaxf(m[0], mx0), mn1 = fmaxf(m[1], mx1);
    float c0 = exp2f(m[0] - mn0), c1 = exp2f(m[1] - mn1);
    float rs0 = 0.f, rs1 = 0.f;
#pragma unroll
    for (int jn = 0; jn < 8; jn++) {
        s[jn][0] = exp2f(s[jn][0] - mn0);
        s[jn][1] = exp2f(s[jn][1] - mn0);
        s[jn][2] = exp2f(s[jn][2] - mn1);
        s[jn][3] = exp2f(s[jn][3] - mn1);
        rs0 += s[jn][0] + s[jn][1];
        rs1 += s[jn][2] + s[jn][3];
    }
    rs0 += __shfl_xor_sync(0xffffffffu, rs0, 1);
    rs0 += __shfl_xor_sync(0xffffffffu, rs0, 2);
    rs1 += __shfl_xor_sync(0xffffffffu, rs1, 1);
    rs1 += __shfl_xor_sync(0xffffffffu, rs1, 2);
    l[0] = l[0] * c0 + rs0; m[0] = mn0;
    l[1] = l[1] * c1 + rs1; m[1] = mn1;
#pragma unroll
    for (int jn = 0; jn < 8; jn++) {
        O[jn][0] *= c0; O[jn][1] *= c0;
        O[jn][2] *= c1; O[jn][3] *= c1;
    }
}

__global__ void __launch_bounds__(128) diff_attn_f16(const float* __restrict__ subln_w) {
    extern __shared__ u32 smem_u[];
    const u32 att_sbase = (u32)__cvta_generic_to_shared(smem_u);

    const int h = blockIdx.y;
    const int hk = h >> 2;                 // NREP = 4
    const int tid = threadIdx.x;
    const int warp = tid >> 5, lane = tid & 31;
    const int g = lane >> 2, q = lane & 3;
    const float lam = g_lambda;

    // async stage loader for K1/K2/V tile kb into stage stg
    auto issue_tile = [&](int stg, int kb) {
        u32 sb = att_sbase + stg * (STAGE_U * 4);
#pragma unroll
        for (int it = 0; it < 12; it++) {
            int idx = tid + it * 128;          // 0..1535
            int arr = idx >> 9;
            int rem = idx & 511;
            int row = rem >> 3;
            int c4 = (rem & 7) * 4;            // u32 offset within row
            const void* src;
            u32 doff;
            if (arr == 0) {
                src = (const u32*)g_kph + (size_t)(kb * 64 + row) * 512 + hk * 32 + c4;
                doff = row * KSTR + c4;
            } else if (arr == 1) {
                src = (const u32*)g_kph + (size_t)(kb * 64 + row) * 512 + 256 + hk * 32 + c4;
                doff = TILE_U + row * KSTR + c4;
            } else {
                src = (const u32*)g_vth + (size_t)(hk * 64 + row) * 1024 + kb * 32 + c4;
                doff = 2 * TILE_U + row * KSTR + c4;
            }
            cp_async16s(sb + doff * 4, src);
        }
        asm volatile("cp.async.commit_group;");
    };

#pragma unroll 1
    for (int seg = 0; seg < 2; seg++) {
        const int qb = seg == 0 ? (int)blockIdx.x : 31 - (int)blockIdx.x;
        const int r0 = qb * 64 + warp * 16 + g;
        const int r1 = r0 + 8;

        // Q fragments from global fp16 (pre-scaled by 0.125*log2e)
        u32 qa1[4][4], qa2[4][4];
        {
            const u32* b0 = (const u32*)g_qph + (size_t)r0 * 2048 + h * 32;
            const u32* b1 = (const u32*)g_qph + (size_t)r1 * 2048 + h * 32;
#pragma unroll
            for (int t = 0; t < 4; t++) {
                qa1[t][0] = b0[8 * t + q];
                qa1[t][1] = b1[8 * t + q];
                qa1[t][2] = b0[8 * t + 4 + q];
                qa1[t][3] = b1[8 * t + 4 + q];
                qa2[t][0] = b0[1024 + 8 * t + q];
                qa2[t][1] = b1[1024 + 8 * t + q];
                qa2[t][2] = b0[1024 + 8 * t + 4 + q];
                qa2[t][3] = b1[1024 + 8 * t + 4 + q];
            }
        }

        float O1[8][4] = {}, O2[8][4] = {};
        float m1[2] = {-1e30f, -1e30f}, l1[2] = {0.f, 0.f};
        float m2[2] = {-1e30f, -1e30f}, l2[2] = {0.f, 0.f};

        issue_tile(0, 0);
        for (int kb = 0; kb <= qb; kb++) {
            const int st = kb & 1;
            if (kb < qb) {
                issue_tile(1 - st, kb + 1);
                asm volatile("cp.async.wait_group 1;");
            } else {
                asm volatile("cp.async.wait_group 0;");
            }
            __syncthreads();

            const u32* sK1 = smem_u + st * STAGE_U;
            const u32* sK2 = sK1 + TILE_U;
            const u32* sV  = sK2 + TILE_U;

            // --- scores, single fp16 pass per stream ---
            float s1[8][4] = {}, s2[8][4] = {};
#pragma unroll
            for (int t = 0; t < 4; t++) {
#pragma unroll
                for (int jn = 0; jn < 8; jn++) {
                    int n = 8 * jn + g;
                    u32 b1f[2] = { sK1[n * KSTR + 8 * t + q], sK1[n * KSTR + 8 * t + 4 + q] };
                    mma_f16(s1[jn], qa1[t], b1f);
                    u32 b2f[2] = { sK2[n * KSTR + 8 * t + q], sK2[n * KSTR + 8 * t + 4 + q] };
                    mma_f16(s2[jn], qa2[t], b2f);
                }
            }

            if (kb == qb) {
#pragma unroll
                for (int jn = 0; jn < 8; jn++) {
                    int c0 = kb * 64 + 8 * jn + 2 * q;
                    if (c0 > r0)     { s1[jn][0] = -1e30f; s2[jn][0] = -1e30f; }
                    if (c0 + 1 > r0) { s1[jn][1] = -1e30f; s2[jn][1] = -1e30f; }
                    if (c0 > r1)     { s1[jn][2] = -1e30f; s2[jn][2] = -1e30f; }
                    if (c0 + 1 > r1) { s1[jn][3] = -1e30f; s2[jn][3] = -1e30f; }
                }
            }

            online_softmax2(s1, m1, l1, O1);
            online_softmax2(s2, m2, l2, O2);

            // --- P @ V (shared V fragments), single fp16 pass ---
#pragma unroll
            for (int t = 0; t < 4; t++) {
                u32 p1[4], p2[4];
                p1[0] = h2u(s1[2*t][0],   s1[2*t][1]);
                p1[1] = h2u(s1[2*t][2],   s1[2*t][3]);
                p1[2] = h2u(s1[2*t+1][0], s1[2*t+1][1]);
                p1[3] = h2u(s1[2*t+1][2], s1[2*t+1][3]);
                p2[0] = h2u(s2[2*t][0],   s2[2*t][1]);
                p2[1] = h2u(s2[2*t][2],   s2[2*t][3]);
                p2[2] = h2u(s2[2*t+1][0], s2[2*t+1][1]);
                p2[3] = h2u(s2[2*t+1][2], s2[2*t+1][3]);
#pragma unroll
                for (int jn = 0; jn < 8; jn++) {
                    int n = 8 * jn + g;
                    u32 vb[2] = { sV[n * KSTR + 8 * t + q], sV[n * KSTR + 8 * t + 4 + q] };
                    mma_f16(O1[jn], p1, vb);
                    mma_f16(O2[jn], p2, vb);
                }
            }
            __syncthreads();   // all consumers done before this stage is re-filled
        }

        // epilogue: diff, RMSNorm over D, subln, (1-lambda_init); fp16 out for Wo gemm
        const float il10 = 1.f / l1[0], il11 = 1.f / l1[1];
        const float il20 = 1.f / l2[0], il21 = 1.f / l2[1];
        float oA[8][2], oB[8][2];
        float ss0 = 0.f, ss1 = 0.f;
#pragma unroll
        for (int jn = 0; jn < 8; jn++) {
            float a0 = O1[jn][0] * il10 - lam * (O2[jn][0] * il20);
            float a1 = O1[jn][1] * il10 - lam * (O2[jn][1] * il20);
            float b0 = O1[jn][2] * il11 - lam * (O2[jn][2] * il21);
            float b1 = O1[jn][3] * il11 - lam * (O2[jn][3] * il21);
            oA[jn][0] = a0; oA[jn][1] = a1;
            oB[jn][0] = b0; oB[jn][1] = b1;
            ss0 += a0 * a0 + a1 * a1;
            ss1 += b0 * b0 + b1 * b1;
        }
        ss0 += __shfl_xor_sync(0xffffffffu, ss0, 1);
        ss0 += __shfl_xor_sync(0xffffffffu, ss0, 2);
        ss1 += __shfl_xor_sync(0xffffffffu, ss1, 1);
        ss1 += __shfl_xor_sync(0xffffffffu, ss1, 2);
        float k0 = rsqrtf(ss0 * (1.0f / 64.0f) + 1e-6f) * (1.0f - LAMBDA_INIT);
        float k1 = rsqrtf(ss1 * (1.0f / 64.0f) + 1e-6f) * (1.0f - LAMBDA_INIT);
#pragma unroll
        for (int jn = 0; jn < 8; jn++) {
            int col = 8 * jn + 2 * q;
            float w0 = subln_w[col], w1 = subln_w[col + 1];
            u32 pa = h2u(oA[jn][0] * k0 * w0, oA[jn][1] * k0 * w1);
            u32 pb = h2u(oB[jn][0] * k1 * w0, oB[jn][1] * k1 * w1);
            *(u32*)(g_at_p + (size_t)r0 * HID_ + h * 64 + col) = pa;
            *(u32*)(g_at_p + (size_t)r1 * HID_ + h * 64 + col) = pb;
        }
        __syncthreads();   // drain before next segment reuses stage 0
    }
}

// ---------------- launch ----------------
extern "C" void kernel_launch(void* const* d_in, const int* in_sizes, int n_in,
                              void* d_out, int out_size) {
    const float* hs   = (const float*)d_in[0];
    const float* Wq   = (const float*)d_in[1];
    const float* Wk   = (const float*)d_in[2];
    const float* Wv   = (const float*)d_in[3];
    const float* Wo   = (const float*)d_in[4];
    const float* lq1  = (const float*)d_in[5];
    const float* lk1  = (const float*)d_in[6];
    const float* lq2  = (const float*)d_in[7];
    const float* lk2  = (const float*)d_in[8];
    const float* subw = (const float*)d_in[9];
    float* out = (float*)d_out;

    void *pqkv, *phsp, *pwp, *pwop, *patp;
    cudaGetSymbolAddress(&pqkv, g_qkv);
    cudaGetSymbolAddress(&phsp, g_hs_p);
    cudaGetSymbolAddress(&pwp, g_w_p);
    cudaGetSymbolAddress(&pwop, g_wo_p);
    cudaGetSymbolAddress(&patp, g_at_p);
    cudaFuncSetAttribute(diff_attn_f16,
                         cudaFuncAttributeMaxDynamicSharedMemorySize, ATT_SMEM_BYTES);

    // pack all fp32 inputs to fp16 in one launch
    pack_all<<<(PACK_TOTAL + 255) / 256, 256>>>((const float2*)hs, (const float2*)Wq,
                                                (const float2*)Wk, (const float2*)Wv,
                                                (const float2*)Wo);

    // fused QKV projection: C[S, 5632]
    gemm_f16<<<dim3(NQKV / 128, S_LEN / 128), 256, GEMM_SMEM_BYTES>>>(
        (const __half*)phsp, (const __half*)pwp, (float*)pqkv, S_LEN, NQKV, HID_);

    // rope q (exp2-scale folded) + rope k + transpose-pack v, one launch
    rope_all<<<(ROPE_TOTAL + 255) / 256, 256>>>();

    lambda_kernel<<<1, 32>>>(lq1, lk1, lq2, lk2);

    // attention: causal-paired grid (16 pair-slots, 32 heads)
    diff_attn_f16<<<dim3(16, 32), 128, ATT_SMEM_BYTES>>>(subw);

    // output projection
    gemm_f16<<<dim3(HID_ / 128, S_LEN / 128), 256, GEMM_SMEM_BYTES>>>(
        (const __half*)patp, (const __half*)pwop, out, S_LEN, HID_, HID_);
}